// round 2
// baseline (speedup 1.0000x reference)
#include <cuda_runtime.h>
#include <cstdint>

// ---------------------------------------------------------------------------
// GAT layer, algebraically reduced:
//   softmax_j(dst[i] + src[j] + c, masked by adj)
//     == adj[i,j]*E[j] / sum_j adj[i,j]*E[j]      (i-only terms cancel)
//   out[b,i,:] = (adj @ (E*h_sum)) / (N * (adj @ E))
// h_sum / src need only a D->65 reduced projection.
// Heavy op: per-batch [4096x4096] @ [4096x80] via mma.sync tf32.
// ---------------------------------------------------------------------------

#define BATCH 4
#define NNODE 4096
#define DD    256
#define NP    80            // padded col count: 64 h_sum + 1 E + 15 zero
#define BM    128
#define BN    80
#define BK    32
#define STAGES 4
#define THREADS 256
#define AS    36            // smem row stride (floats): bank = (4g+t)%32, conflict-free
#define A_STG (BM * AS)     // 4608 floats
#define B_STG (NP * AS)     // 2880 floats
#define SMEM_FLOATS (STAGES * (A_STG + B_STG) + BM)
#define SMEM_BYTES  (SMEM_FLOATS * 4)

__device__ float d_Mred[NP * DD];            // [c][d], tf32-rounded (rows 65..79 zero)
__device__ float d_biasv[NP];
__device__ float d_y[16384 * NP];            // projection output, stride NP
__device__ float d_gt[BATCH * NP * NNODE];   // transposed transformed g
__device__ float d_srcmax[BATCH];

// ------------------------------ helpers -----------------------------------
__device__ __forceinline__ unsigned su32(const void* p) {
    return (unsigned)__cvta_generic_to_shared(p);
}
__device__ __forceinline__ void cpa16(unsigned d, const float* s) {
    asm volatile("cp.async.cg.shared.global [%0], [%1], 16;\n" :: "r"(d), "l"(s));
}
__device__ __forceinline__ void cpcommit() {
    asm volatile("cp.async.commit_group;\n" ::);
}
template<int W> __device__ __forceinline__ void cpwait() {
    asm volatile("cp.async.wait_group %0;\n" :: "n"(W));
}
__device__ __forceinline__ void mma8(float* d, const unsigned* a, const unsigned* b) {
    asm volatile("mma.sync.aligned.m16n8k8.row.col.f32.tf32.tf32.f32 "
                 "{%0,%1,%2,%3}, {%4,%5,%6,%7}, {%8,%9}, {%0,%1,%2,%3};\n"
                 : "+f"(d[0]), "+f"(d[1]), "+f"(d[2]), "+f"(d[3])
                 : "r"(a[0]), "r"(a[1]), "r"(a[2]), "r"(a[3]),
                   "r"(b[0]), "r"(b[1]));
}
__device__ __forceinline__ float tf32rna(float x) {
    unsigned u; asm("cvt.rna.tf32.f32 %0, %1;\n" : "=r"(u) : "f"(x));
    return __uint_as_float(u);
}

// ------------------------------ prep --------------------------------------
// Mred[c][d]: c<64 -> sum_h W_fc[h*64+c][d]; c==64 -> sum_r W_fc[r][d]*ws[r].
// ws[h*64+o] = 0.25 * sum_k W_attn[k*512 + h*128 + o]  (src half, head-mean).
__global__ void prep_kernel(const float* __restrict__ W_fc,
                            const float* __restrict__ b_fc,
                            const float* __restrict__ W_attn) {
    __shared__ float ws[256];
    const int tid = threadIdx.x;
    {
        int h = tid >> 6, o = tid & 63;
        ws[tid] = 0.25f * (W_attn[       h * 128 + o] +
                           W_attn[ 512 + h * 128 + o] +
                           W_attn[1024 + h * 128 + o] +
                           W_attn[1536 + h * 128 + o]);
    }
    __syncthreads();
    for (int idx = tid; idx < NP * DD; idx += 256) {
        int c = idx / DD, d = idx - c * DD;
        float v = 0.f;
        if (c < 64) {
            v = W_fc[c * DD + d] + W_fc[(64 + c) * DD + d] +
                W_fc[(128 + c) * DD + d] + W_fc[(192 + c) * DD + d];
        } else if (c == 64) {
            for (int r = 0; r < 256; r++) v += W_fc[r * DD + d] * ws[r];
        }
        d_Mred[idx] = tf32rna(v);
    }
    if (tid < NP) {
        float v = 0.f;
        if (tid < 64) {
            v = b_fc[tid] + b_fc[64 + tid] + b_fc[128 + tid] + b_fc[192 + tid];
        } else if (tid == 64) {
            for (int r = 0; r < 256; r++) v += b_fc[r] * ws[r];
        }
        d_biasv[tid] = v;
    }
}

// --------------------------- per-batch src max -----------------------------
__global__ void srcmax_kernel() {
    __shared__ float red[256];
    const int b = blockIdx.x, tid = threadIdx.x;
    float m = -1e30f;
    for (int j = tid; j < NNODE; j += 256)
        m = fmaxf(m, d_y[((long)b * NNODE + j) * NP + 64]);
    red[tid] = m; __syncthreads();
    for (int s = 128; s > 0; s >>= 1) {
        if (tid < s) red[tid] = fmaxf(red[tid], red[tid + s]);
        __syncthreads();
    }
    if (tid == 0) d_srcmax[b] = red[0];
}

// --------------------------- transform -> gt (transposed) ------------------
// gt[b][c][j] = tf32(E_j * y[j][c]) for c<64; c==64 -> tf32(E_j); c>64 -> 0.
__global__ void transform_kernel() {
    __shared__ float ys[64 * 81];
    __shared__ float e[64];
    const int tid = threadIdx.x;
    const int base = blockIdx.x * 64;          // global node base
    const int b = base >> 12;                  // /4096
    const float* src = d_y + (long)base * NP;
    for (int idx = tid; idx < 64 * NP; idx += 256) {
        int r = idx / NP, c = idx - r * NP;
        ys[r * 81 + c] = src[idx];
    }
    __syncthreads();
    if (tid < 64) e[tid] = __expf(ys[tid * 81 + 64] - d_srcmax[b]);
    __syncthreads();
    float* gbase = d_gt + (long)b * NP * NNODE + (base & (NNODE - 1));
    const int j = tid & 63;
    #pragma unroll
    for (int it = 0; it < 20; it++) {
        int c = it * 4 + (tid >> 6);
        float v;
        if (c < 64)       v = tf32rna(e[j] * ys[j * 81 + c]);
        else if (c == 64) v = tf32rna(e[j]);
        else              v = 0.f;
        gbase[(long)c * NNODE + j] = v;
    }
}

// --------------------------- tf32 GEMM ------------------------------------
// MODE 0: y[16384 x 80] = features[16384 x 256] @ Mred^T + bias
// MODE 1: out = (adj @ gt^T) / (N * Z), Z fused from column 64
template<int MODE>
__global__ __launch_bounds__(THREADS, 1)
void gemm_kernel(const float* __restrict__ Abase, float* __restrict__ OutP)
{
    constexpr int lda = (MODE == 0) ? DD : NNODE;
    constexpr int ldb = (MODE == 0) ? DD : NNODE;
    constexpr int KT  = (MODE == 0) ? (DD / BK) : (NNODE / BK);
    extern __shared__ float sm[];
    float* Zs = sm + STAGES * (A_STG + B_STG);

    const int mtile = blockIdx.x;
    const int batch = blockIdx.y;
    const int tid = threadIdx.x;
    const int wid = tid >> 5, lane = tid & 31;
    const int wm = wid & 3, wn = wid >> 2;
    const int g = lane >> 2, t = lane & 3;

    const float* A  = Abase + (MODE == 1 ? (long)batch * NNODE * NNODE : 0L)
                            + (long)mtile * BM * lda;
    const float* Bt = (MODE == 0) ? d_Mred : (d_gt + (long)batch * NP * NNODE);

    auto stage = [&](int s, int kt) {
        float* as = sm + s * A_STG;
        float* bs = sm + STAGES * A_STG + s * B_STG;
        const float* ag = A + kt * BK;
        #pragma unroll 4
        for (int idx = tid; idx < BM * 8; idx += THREADS) {
            int r = idx >> 3, sg = idx & 7;
            cpa16(su32(as + r * AS + sg * 4), ag + (long)r * lda + sg * 4);
        }
        const float* bg = Bt + kt * BK;
        #pragma unroll 3
        for (int idx = tid; idx < NP * 8; idx += THREADS) {
            int r = idx >> 3, sg = idx & 7;
            cpa16(su32(bs + r * AS + sg * 4), bg + (long)r * ldb + sg * 4);
        }
    };

    int kt = 0;
    for (int s = 0; s < STAGES - 1; s++) { stage(s, kt); kt++; cpcommit(); }

    float acc[2][5][4] = {};
    const int arow0 = wm * 32 + g;
    const int bcol0 = wn * 40 + g;

    for (int k = 0; k < KT; k++) {
        cpwait<STAGES - 2>();
        __syncthreads();
        if (kt < KT) { stage(kt % STAGES, kt); kt++; }
        cpcommit();
        const float* as = sm + (k % STAGES) * A_STG;
        const float* bs = sm + STAGES * A_STG + (k % STAGES) * B_STG;
        #pragma unroll
        for (int kk = 0; kk < 4; kk++) {
            unsigned af[2][4], bf[5][2];
            #pragma unroll
            for (int i = 0; i < 2; i++) {
                const float* p = as + (arow0 + i * 16) * AS + kk * 8 + t;
                af[i][0] = __float_as_uint(p[0]);
                af[i][1] = __float_as_uint(p[8 * AS]);
                af[i][2] = __float_as_uint(p[4]);
                af[i][3] = __float_as_uint(p[8 * AS + 4]);
            }
            #pragma unroll
            for (int j = 0; j < 5; j++) {
                const float* p = bs + (bcol0 + j * 8) * AS + kk * 8 + t;
                bf[j][0] = __float_as_uint(p[0]);
                bf[j][1] = __float_as_uint(p[4]);
            }
            #pragma unroll
            for (int i = 0; i < 2; i++)
                #pragma unroll
                for (int j = 0; j < 5; j++)
                    mma8(acc[i][j], af[i], bf[j]);
        }
    }

    if (MODE == 0) {
        float* O = d_y;
        #pragma unroll
        for (int i = 0; i < 2; i++)
            #pragma unroll
            for (int j = 0; j < 5; j++) {
                int colb = wn * 40 + j * 8 + t * 2;
                #pragma unroll
                for (int kq = 0; kq < 4; kq++) {
                    int col = colb + (kq & 1);
                    int row = mtile * BM + wm * 32 + i * 16 + g + ((kq >> 1) * 8);
                    if (col < 65)
                        O[(long)row * NP + col] = acc[i][j][kq] + d_biasv[col];
                }
            }
    } else {
        // stash Z (column 64 = warp-n 1, frag j=3, col-in-frag 0 -> t==0, c0/c2)
        if (wn == 1 && t == 0) {
            #pragma unroll
            for (int i = 0; i < 2; i++) {
                Zs[wm * 32 + i * 16 + g]     = acc[i][3][0];
                Zs[wm * 32 + i * 16 + g + 8] = acc[i][3][2];
            }
        }
        __syncthreads();
        #pragma unroll
        for (int i = 0; i < 2; i++) {
            float rz0 = 1.0f / (4096.0f * Zs[wm * 32 + i * 16 + g]);
            float rz1 = 1.0f / (4096.0f * Zs[wm * 32 + i * 16 + g + 8]);
            #pragma unroll
            for (int j = 0; j < 5; j++) {
                int colb = wn * 40 + j * 8 + t * 2;
                if (colb >= 64) continue;   // cols 64..79 are Z/padding
                #pragma unroll
                for (int kq = 0; kq < 4; kq++) {
                    int col  = colb + (kq & 1);
                    int rowl = wm * 32 + i * 16 + g + ((kq >> 1) * 8);
                    long row = (long)batch * NNODE + mtile * BM + rowl;
                    OutP[row * 64 + col] = acc[i][j][kq] * ((kq >> 1) ? rz1 : rz0);
                }
            }
        }
    }
}

// ------------------------------ launch ------------------------------------
extern "C" void kernel_launch(void* const* d_in, const int* in_sizes, int n_in,
                              void* d_out, int out_size) {
    const float* features = (const float*)d_in[0];
    const float* adj      = (const float*)d_in[1];
    const float* W_fc     = (const float*)d_in[2];
    const float* b_fc     = (const float*)d_in[3];
    const float* W_attn   = (const float*)d_in[4];
    // d_in[5] = b_attn: cancels in the softmax.
    float* out = (float*)d_out;

    cudaFuncSetAttribute(gemm_kernel<0>,
                         cudaFuncAttributeMaxDynamicSharedMemorySize, SMEM_BYTES);
    cudaFuncSetAttribute(gemm_kernel<1>,
                         cudaFuncAttributeMaxDynamicSharedMemorySize, SMEM_BYTES);

    prep_kernel<<<1, 256>>>(W_fc, b_fc, W_attn);
    gemm_kernel<0><<<dim3(16384 / BM, 1), THREADS, SMEM_BYTES>>>(features, nullptr);
    srcmax_kernel<<<BATCH, 256>>>();
    transform_kernel<<<16384 / 64, 256>>>();
    gemm_kernel<1><<<dim3(NNODE / BM, BATCH), THREADS, SMEM_BYTES>>>(adj, out);
}